// round 1
// baseline (speedup 1.0000x reference)
#include <cuda_runtime.h>
#include <math.h>

// Geometry: (B=2, C=1, 192, 192, 192) per tensor; 4 volumes total to skeletonize
// (target b0, target b1, pred b0, pred b1).
constexpr int DIM   = 192;
constexpr int SLICE = DIM * DIM;            // 36864
constexpr int NVOX  = DIM * DIM * DIM;      // 7077888 per volume
constexpr int NTOT  = 4 * NVOX;             // 28311552
constexpr int N2    = 2 * NVOX;             // elements per input tensor

// Scratch (device globals: allocation-free per harness rules)
__device__ float  g_X[NTOT];   // working skeleton state: [0,2N)=target, [2N,4N)=pred
__device__ float  g_M[NTOT];   // 7-point min-pool result
__device__ double g_acc[4];    // {sum(skelT*pred), sum(skelT), sum(skelP*target), sum(skelP)}

__global__ void init_kernel(const float* __restrict__ pred,
                            const float* __restrict__ target) {
    int i = blockIdx.x * blockDim.x + threadIdx.x;
    if (i < N2) {
        g_X[i]      = target[i];
        g_X[N2 + i] = pred[i];
    }
}

// Kernel A: M = min over {center, d±1, h±1, w±1} (clamped == +inf padding)
__global__ void minpool_kernel() {
    int i = blockIdx.x * blockDim.x + threadIdx.x;
    if (i >= NTOT) return;
    int r = i % NVOX;           // index within its volume
    int w = r % DIM;
    int h = (r / DIM) % DIM;
    int d = r / SLICE;

    float m = g_X[i];
    if (w > 0)       m = fminf(m, g_X[i - 1]);
    if (w < DIM - 1) m = fminf(m, g_X[i + 1]);
    if (h > 0)       m = fminf(m, g_X[i - DIM]);
    if (h < DIM - 1) m = fminf(m, g_X[i + DIM]);
    if (d > 0)       m = fminf(m, g_X[i - SLICE]);
    if (d < DIM - 1) m = fminf(m, g_X[i + SLICE]);
    g_M[i] = m;
}

// Kernel B: x = relu(x - relu(maxpool3x3x3(M) - M)), in place on g_X.
__global__ void update_kernel() {
    int i = blockIdx.x * blockDim.x + threadIdx.x;
    if (i >= NTOT) return;
    int r = i % NVOX;
    int w = r % DIM;
    int h = (r / DIM) % DIM;
    int d = r / SLICE;

    int dlo = (d > 0) ? -1 : 0, dhi = (d < DIM - 1) ? 1 : 0;
    int hlo = (h > 0) ? -1 : 0, hhi = (h < DIM - 1) ? 1 : 0;
    int wlo = (w > 0) ? -1 : 0, whi = (w < DIM - 1) ? 1 : 0;

    float mx = -INFINITY;
    for (int dz = dlo; dz <= dhi; ++dz) {
        int bz = i + dz * SLICE;
        for (int dy = hlo; dy <= hhi; ++dy) {
            int by = bz + dy * DIM;
            for (int dx = wlo; dx <= whi; ++dx) {
                mx = fmaxf(mx, g_M[by + dx]);
            }
        }
    }
    float m = g_M[i];
    float contour = fmaxf(mx - m, 0.0f);      // mx >= m always (center in window)
    g_X[i] = fmaxf(g_X[i] - contour, 0.0f);
}

__global__ void zero_acc_kernel() {
    int t = threadIdx.x;
    if (t < 4) g_acc[t] = 0.0;
}

__global__ void reduce_kernel(const float* __restrict__ pred,
                              const float* __restrict__ target) {
    __shared__ double sh[4 * 256];
    int tid = threadIdx.x;
    double a0 = 0.0, a1 = 0.0, a2 = 0.0, a3 = 0.0;
    for (int i = blockIdx.x * blockDim.x + tid; i < N2;
         i += gridDim.x * blockDim.x) {
        float st = g_X[i];         // skeleton(target)
        float sp = g_X[N2 + i];    // skeleton(pred)
        float p  = pred[i];
        float t  = target[i];
        a0 += (double)(st * p);
        a1 += (double)st;
        a2 += (double)(sp * t);
        a3 += (double)sp;
    }
    sh[tid]       = a0;
    sh[256 + tid] = a1;
    sh[512 + tid] = a2;
    sh[768 + tid] = a3;
    __syncthreads();
    for (int s = 128; s > 0; s >>= 1) {
        if (tid < s) {
            sh[tid]       += sh[tid + s];
            sh[256 + tid] += sh[256 + tid + s];
            sh[512 + tid] += sh[512 + tid + s];
            sh[768 + tid] += sh[768 + tid + s];
        }
        __syncthreads();
    }
    if (tid == 0) {
        atomicAdd(&g_acc[0], sh[0]);
        atomicAdd(&g_acc[1], sh[256]);
        atomicAdd(&g_acc[2], sh[512]);
        atomicAdd(&g_acc[3], sh[768]);
    }
}

__global__ void final_kernel(float* __restrict__ out) {
    double clrecall = (g_acc[0] + 1e-12) / (g_acc[1] + 1e-12);
    double clacc    = (g_acc[2] + 1e-12) / (g_acc[3] + 1e-12);
    double cldice   = 2.0 * clrecall * clacc / (clrecall + clacc);
    out[0] = (float)(1.0 - cldice);
}

extern "C" void kernel_launch(void* const* d_in, const int* in_sizes, int n_in,
                              void* d_out, int out_size) {
    const float* pred   = (const float*)d_in[0];
    const float* target = (const float*)d_in[1];
    float* out = (float*)d_out;

    const int T = 256;
    init_kernel<<<(N2 + T - 1) / T, T>>>(pred, target);

    for (int it = 0; it < 5; ++it) {
        minpool_kernel<<<(NTOT + T - 1) / T, T>>>();
        update_kernel<<<(NTOT + T - 1) / T, T>>>();
    }

    zero_acc_kernel<<<1, 32>>>();
    reduce_kernel<<<2048, 256>>>(pred, target);
    final_kernel<<<1, 1>>>(out);
}

// round 2
// speedup vs baseline: 1.8094x; 1.8094x over previous
#include <cuda_runtime.h>
#include <math.h>

constexpr int DIM   = 192;
constexpr int SLICE = DIM * DIM;
constexpr int NVOX  = DIM * DIM * DIM;

constexpr int TX = 32, TY = 16;
constexpr int HX = TX + 4, HY = TY + 4;   // x-slice tile with halo-2: 36 x 20
constexpr int MX = TX + 2, MY = TY + 2;   // M tile with halo-1: 34 x 18
constexpr int RX = TX,     RY = TY + 2;   // row-max tile: 32 x 18
constexpr int NT = TX * TY;               // 512 threads

__device__ float  g_X[4 * NVOX];   // 4 volumes: [0,1]=target b0/b1, [2,3]=pred b0/b1
__device__ double g_acc[4];        // {sum(skelT*pred), sum(skelT), sum(skelP*target), sum(skelP)}

__device__ __forceinline__ int slot3(int z) { return ((z % 3) + 3) % 3; }

// MODE 0: first iteration  (src = raw inputs, write g_X)
// MODE 1: middle iteration (src = g_X, write g_X)
// MODE 2: last iteration   (src = g_X, no write; accumulate sums)
template <int MODE>
__global__ __launch_bounds__(NT) void fused_iter(const float* __restrict__ pred,
                                                 const float* __restrict__ target) {
    __shared__ float xs[3][HY * HX];   // rolling x slices (halo-2)
    __shared__ float Ms[MY * MX];      // 7-pt min plane (halo-1)
    __shared__ float Rb[RY * RX];      // row (x-dir) max of M
    __shared__ float As[3][NT];        // rolling 2D (3x3) max of M
    __shared__ float Mc[3][NT];        // rolling M center values
    __shared__ double shred[NT];       // reduction scratch (MODE 2)

    const int tx = threadIdx.x, ty = threadIdx.y;
    const int t  = ty * TX + tx;
    const int gx0 = blockIdx.x * TX, gy0 = blockIdx.y * TY;
    const int v   = blockIdx.z;

    const float* src;
    if (MODE == 0) src = (v < 2) ? (target + (size_t)v * NVOX)
                                 : (pred + (size_t)(v - 2) * NVOX);
    else           src = g_X + (size_t)v * NVOX;
    float* dst = g_X + (size_t)v * NVOX;
    const float* other = nullptr;
    if (MODE == 2) other = (v < 2) ? (pred + (size_t)v * NVOX)
                                   : (target + (size_t)(v - 2) * NVOX);

    double accS = 0.0, accP = 0.0;

    // ---- helpers ----
    auto loadX = [&](int z, int s) {
        #pragma unroll
        for (int i = t; i < HY * HX; i += NT) {
            int ly = i / HX, lx = i % HX;
            int gy = gy0 + ly - 2, gx = gx0 + lx - 2;
            float val = INFINITY;
            if ((unsigned)z < (unsigned)DIM && (unsigned)gy < (unsigned)DIM &&
                (unsigned)gx < (unsigned)DIM)
                val = __ldg(&src[(size_t)z * SLICE + gy * DIM + gx]);
            xs[s][i] = val;
        }
    };
    auto computeM = [&](int zz) {
        int sA = slot3(zz - 1), sB = slot3(zz), sC = slot3(zz + 1);
        #pragma unroll
        for (int i = t; i < MY * MX; i += NT) {
            int ly = i / MX, lx = i % MX;
            int gy = gy0 + ly - 1, gx = gx0 + lx - 1;
            float m;
            if ((unsigned)gy >= (unsigned)DIM || (unsigned)gx >= (unsigned)DIM) {
                m = -INFINITY;   // outside volume: identity for the max stage
            } else {
                int xi = (ly + 1) * HX + (lx + 1);
                float c = xs[sB][xi];
                m = fminf(c, xs[sA][xi]);
                m = fminf(m, xs[sC][xi]);
                m = fminf(m, xs[sB][xi - 1]);
                m = fminf(m, xs[sB][xi + 1]);
                m = fminf(m, xs[sB][xi - HX]);
                m = fminf(m, xs[sB][xi + HX]);
            }
            Ms[i] = m;
        }
    };
    auto computeR = [&]() {
        #pragma unroll
        for (int i = t; i < RY * RX; i += NT) {
            int ly = i / RX, lx = i % RX;
            int mi = ly * MX + lx;   // M x-range starts one to the left
            Rb[i] = fmaxf(fmaxf(Ms[mi], Ms[mi + 1]), Ms[mi + 2]);
        }
    };
    auto computeA = [&](int zz) {
        int s = slot3(zz);
        // NT == TY*TX: exactly one element per thread
        int ri = ty * RX + tx;
        As[s][t] = fmaxf(fmaxf(Rb[ri], Rb[ri + RX]), Rb[ri + 2 * RX]);
        Mc[s][t] = Ms[(ty + 1) * MX + (tx + 1)];
    };

    // ---- prologue: produce plane 0 ----
    #pragma unroll
    for (int i = t; i < HY * HX; i += NT) xs[2][i] = INFINITY;  // x(-1)
    loadX(0, 0);
    loadX(1, 1);
    As[2][t] = -INFINITY;                                        // A(-1)
    __syncthreads();
    computeM(0);
    __syncthreads();
    computeR();
    __syncthreads();
    computeA(0);

    // ---- main sweep ----
    for (int z = 0; z < DIM; ++z) {
        int zz = z + 1;   // plane to produce this step
        __syncthreads();
        if (zz < DIM) {
            loadX(zz + 1, slot3(zz + 1));   // fills +inf when zz+1 == DIM
            __syncthreads();
            computeM(zz);
            __syncthreads();
            computeR();
            __syncthreads();
            computeA(zz);
        } else {
            As[slot3(zz)][t] = -INFINITY;   // A(192)
        }
        __syncthreads();

        // update plane z
        float a = fmaxf(fmaxf(As[slot3(z - 1)][t], As[slot3(z)][t]),
                        As[slot3(z + 1)][t]);
        float contour = fmaxf(a - Mc[slot3(z)][t], 0.0f);
        float xc = xs[slot3(z)][(ty + 2) * HX + (tx + 2)];
        float o = fmaxf(xc - contour, 0.0f);

        size_t gidx = (size_t)z * SLICE + (gy0 + ty) * DIM + (gx0 + tx);
        if (MODE < 2) {
            dst[gidx] = o;
        } else {
            accS += (double)o;
            accP += (double)(o * __ldg(&other[gidx]));
        }
    }

    // ---- MODE 2: block reduce + atomic ----
    if (MODE == 2) {
        __syncthreads();
        shred[t] = accS;
        __syncthreads();
        for (int s = NT / 2; s > 0; s >>= 1) {
            if (t < s) shred[t] += shred[t + s];
            __syncthreads();
        }
        double sumS = shred[0];
        __syncthreads();
        shred[t] = accP;
        __syncthreads();
        for (int s = NT / 2; s > 0; s >>= 1) {
            if (t < s) shred[t] += shred[t + s];
            __syncthreads();
        }
        if (t == 0) {
            double sumP = shred[0];
            if (v < 2) {
                atomicAdd(&g_acc[0], sumP);
                atomicAdd(&g_acc[1], sumS);
            } else {
                atomicAdd(&g_acc[2], sumP);
                atomicAdd(&g_acc[3], sumS);
            }
        }
    }
}

__global__ void zero_acc_kernel() {
    if (threadIdx.x < 4) g_acc[threadIdx.x] = 0.0;
}

__global__ void final_kernel(float* __restrict__ out) {
    double clrecall = (g_acc[0] + 1e-12) / (g_acc[1] + 1e-12);
    double clacc    = (g_acc[2] + 1e-12) / (g_acc[3] + 1e-12);
    double cldice   = 2.0 * clrecall * clacc / (clrecall + clacc);
    out[0] = (float)(1.0 - cldice);
}

extern "C" void kernel_launch(void* const* d_in, const int* in_sizes, int n_in,
                              void* d_out, int out_size) {
    const float* pred   = (const float*)d_in[0];
    const float* target = (const float*)d_in[1];
    float* out = (float*)d_out;

    dim3 blk(TX, TY, 1);
    dim3 grd(DIM / TX, DIM / TY, 4);

    zero_acc_kernel<<<1, 32>>>();
    fused_iter<0><<<grd, blk>>>(pred, target);
    fused_iter<1><<<grd, blk>>>(pred, target);
    fused_iter<1><<<grd, blk>>>(pred, target);
    fused_iter<1><<<grd, blk>>>(pred, target);
    fused_iter<2><<<grd, blk>>>(pred, target);
    final_kernel<<<1, 1>>>(out);
}

// round 3
// speedup vs baseline: 3.5635x; 1.9694x over previous
#include <cuda_runtime.h>
#include <math.h>

constexpr int DIM   = 192;
constexpr int SLICE = DIM * DIM;
constexpr int NVOX  = DIM * DIM * DIM;

constexpr int TX = 32, TY = 16;
constexpr int NT = TX * TY;               // 512 threads
constexpr int HX = TX + 4, HY = TY + 4;   // x-slice halo-2 tile: 36 x 20 (720)
constexpr int MX = TX + 2, MY = TY + 2;   // M-plane halo-1 tile: 34 x 18 (612)
constexpr int CHZ = 48;                   // z-planes per chunk
constexpr int NCH = DIM / CHZ;            // 4 chunks

__device__ float  g_buf[2][4 * NVOX];     // ping-pong state, 4 volumes each
__device__ double g_acc[4];   // {sum(skelT*pred), sum(skelT), sum(skelP*target), sum(skelP)}

__device__ __forceinline__ int slot4(int z) { return (z + 400) & 3; }

// MODE 0: src = raw inputs, write dst
// MODE 1: src = buffer,     write dst
// MODE 2: src = buffer,     no write; accumulate the 4 sums
template <int MODE>
__global__ __launch_bounds__(NT, 3) void fused_iter(int srcSel, int dstSel,
                                                    const float* __restrict__ pred,
                                                    const float* __restrict__ target) {
    __shared__ float xs[4][HY * HX];   // rolling x-slices (halo-2)
    __shared__ float Ms[MY * MX];      // current 7-pt-min plane (halo-1)

    const int tx = threadIdx.x, ty = threadIdx.y;
    const int t  = ty * TX + tx;
    const int gx0 = blockIdx.x * TX, gy0 = blockIdx.y * TY;
    const int chunk = blockIdx.z % NCH;
    const int v     = blockIdx.z / NCH;
    const int z0 = chunk * CHZ, z1 = z0 + CHZ;

    const float* src;
    if (MODE == 0) src = (v < 2) ? (target + (size_t)v * NVOX)
                                 : (pred + (size_t)(v - 2) * NVOX);
    else           src = g_buf[srcSel] + (size_t)v * NVOX;
    float* dst = g_buf[dstSel] + (size_t)v * NVOX;
    const float* other = nullptr;
    if (MODE == 2) other = (v < 2) ? (pred + (size_t)v * NVOX)
                                   : (target + (size_t)(v - 2) * NVOX);

    double accS = 0.0, accP = 0.0;

    auto prefetchX = [&](int z, float rv[2]) {
        #pragma unroll
        for (int k = 0; k < 2; ++k) {
            int i = t + k * NT;
            float val = INFINITY;
            if (i < HY * HX) {
                int ly = i / HX, lx = i % HX;
                int gy = gy0 + ly - 2, gx = gx0 + lx - 2;
                if ((unsigned)z < (unsigned)DIM && (unsigned)gy < (unsigned)DIM &&
                    (unsigned)gx < (unsigned)DIM)
                    val = __ldg(&src[(size_t)z * SLICE + gy * DIM + gx]);
            }
            rv[k] = val;
        }
    };
    auto commitX = [&](int s, const float rv[2]) {
        #pragma unroll
        for (int k = 0; k < 2; ++k) {
            int i = t + k * NT;
            if (i < HY * HX) xs[s][i] = rv[k];
        }
    };
    // M(zz) = 7-pt min of x; out-of-plane entries = -inf (identity for max stage)
    auto computeM = [&](int zz) {
        int sA = slot4(zz - 1), sB = slot4(zz), sC = slot4(zz + 1);
        #pragma unroll
        for (int i = t; i < MY * MX; i += NT) {
            int ly = i / MX, lx = i % MX;
            int gy = gy0 + ly - 1, gx = gx0 + lx - 1;
            float m;
            if ((unsigned)gy >= (unsigned)DIM || (unsigned)gx >= (unsigned)DIM) {
                m = -INFINITY;
            } else {
                int xi = (ly + 1) * HX + (lx + 1);
                m = xs[sB][xi];
                m = fminf(m, xs[sA][xi]);
                m = fminf(m, xs[sC][xi]);
                m = fminf(m, xs[sB][xi - 1]);
                m = fminf(m, xs[sB][xi + 1]);
                m = fminf(m, xs[sB][xi - HX]);
                m = fminf(m, xs[sB][xi + HX]);
            }
            Ms[i] = m;
        }
    };
    // 3x3 in-plane max of M around this thread's column
    auto maxA = [&]() {
        int b = ty * MX + tx;
        float a = Ms[b];
        a = fmaxf(a, Ms[b + 1]);
        a = fmaxf(a, Ms[b + 2]);
        a = fmaxf(a, Ms[b + MX]);
        a = fmaxf(a, Ms[b + MX + 1]);
        a = fmaxf(a, Ms[b + MX + 2]);
        a = fmaxf(a, Ms[b + 2 * MX]);
        a = fmaxf(a, Ms[b + 2 * MX + 1]);
        a = fmaxf(a, Ms[b + 2 * MX + 2]);
        return a;
    };

    // ---- prologue: fill x(z0-2..z0+2), produce a_prev=A(z0-1), a_cur=A(z0) ----
    float a_prev, a_cur, mc_cur;
    {
        float rv[4][2];
        prefetchX(z0 - 2, rv[0]);
        prefetchX(z0 - 1, rv[1]);
        prefetchX(z0,     rv[2]);
        prefetchX(z0 + 1, rv[3]);
        commitX(slot4(z0 - 2), rv[0]);
        commitX(slot4(z0 - 1), rv[1]);
        commitX(slot4(z0),     rv[2]);
        commitX(slot4(z0 + 1), rv[3]);
        __syncthreads();
        if (z0 > 0) computeM(z0 - 1);
        __syncthreads();
        a_prev = (z0 > 0) ? maxA() : -INFINITY;
        __syncthreads();
        float rv2[2];
        prefetchX(z0 + 2, rv2);
        commitX(slot4(z0 + 2), rv2);
        computeM(z0);
        __syncthreads();
        a_cur  = maxA();
        mc_cur = Ms[(ty + 1) * MX + (tx + 1)];
    }

    // ---- main sweep over this chunk ----
    for (int z = z0; z < z1; ++z) {
        float rv[2];
        prefetchX(z + 3, rv);            // global loads before the barrier
        __syncthreads();                 // prior plane's smem reads complete
        commitX(slot4(z + 3), rv);
        if (z + 1 < DIM) computeM(z + 1);
        __syncthreads();                 // Ms(z+1) published

        float a_next, mc_next;
        if (z + 1 < DIM) {
            a_next  = maxA();
            mc_next = Ms[(ty + 1) * MX + (tx + 1)];
        } else {
            a_next  = -INFINITY;
            mc_next = 0.0f;
        }

        float amax    = fmaxf(fmaxf(a_prev, a_cur), a_next);
        float contour = fmaxf(amax - mc_cur, 0.0f);
        float xc = xs[slot4(z)][(ty + 2) * HX + (tx + 2)];
        float o  = fmaxf(xc - contour, 0.0f);

        size_t gidx = (size_t)z * SLICE + (size_t)(gy0 + ty) * DIM + (gx0 + tx);
        if (MODE < 2) {
            dst[gidx] = o;
        } else {
            accS += (double)o;
            accP += (double)(o * __ldg(&other[gidx]));
        }

        a_prev = a_cur; a_cur = a_next; mc_cur = mc_next;
    }

    // ---- MODE 2: warp-shuffle reduce + atomics ----
    if (MODE == 2) {
        #pragma unroll
        for (int off = 16; off > 0; off >>= 1) {
            accS += __shfl_down_sync(0xffffffffu, accS, off);
            accP += __shfl_down_sync(0xffffffffu, accP, off);
        }
        if ((t & 31) == 0) {
            if (v < 2) {
                atomicAdd(&g_acc[0], accP);
                atomicAdd(&g_acc[1], accS);
            } else {
                atomicAdd(&g_acc[2], accP);
                atomicAdd(&g_acc[3], accS);
            }
        }
    }
}

__global__ void zero_acc_kernel() {
    if (threadIdx.x < 4) g_acc[threadIdx.x] = 0.0;
}

__global__ void final_kernel(float* __restrict__ out) {
    double clrecall = (g_acc[0] + 1e-12) / (g_acc[1] + 1e-12);
    double clacc    = (g_acc[2] + 1e-12) / (g_acc[3] + 1e-12);
    double cldice   = 2.0 * clrecall * clacc / (clrecall + clacc);
    out[0] = (float)(1.0 - cldice);
}

extern "C" void kernel_launch(void* const* d_in, const int* in_sizes, int n_in,
                              void* d_out, int out_size) {
    const float* pred   = (const float*)d_in[0];
    const float* target = (const float*)d_in[1];
    float* out = (float*)d_out;

    dim3 blk(TX, TY, 1);
    dim3 grd(DIM / TX, DIM / TY, 4 * NCH);

    zero_acc_kernel<<<1, 32>>>();
    fused_iter<0><<<grd, blk>>>(0, 0, pred, target);   // inputs -> buf0
    fused_iter<1><<<grd, blk>>>(0, 1, pred, target);   // buf0 -> buf1
    fused_iter<1><<<grd, blk>>>(1, 0, pred, target);   // buf1 -> buf0
    fused_iter<1><<<grd, blk>>>(0, 1, pred, target);   // buf0 -> buf1
    fused_iter<2><<<grd, blk>>>(1, 0, pred, target);   // buf1 -> sums
    final_kernel<<<1, 1>>>(out);
}

// round 4
// speedup vs baseline: 4.0517x; 1.1370x over previous
#include <cuda_runtime.h>
#include <math.h>

constexpr int DIM   = 192;
constexpr int SLICE = DIM * DIM;
constexpr int NVOX  = DIM * SLICE;

constexpr int TYT = 8;               // threads in y
constexpr int YPT = 4;               // y rows per thread (tile height 32)
constexpr int OUT = 28;              // output span per tile (32 - 2*2 halo)
constexpr int NB  = (DIM + OUT - 1) / OUT;   // 7 tiles per axis
constexpr int CHZ = 48, NCH = DIM / CHZ;     // 4 z-chunks
constexpr unsigned FULL = 0xffffffffu;

__device__ float  g_buf[2][4 * NVOX];   // ping-pong: 4 volumes (2 target, 2 pred)
__device__ double g_acc[4];  // {sum(skelT*pred), sum(skelT), sum(skelP*target), sum(skelP)}

// MODE 0: src = raw inputs -> dst buffer
// MODE 1: src buffer -> dst buffer
// MODE 2: src buffer -> accumulate sums (no write)
template <int MODE>
__global__ __launch_bounds__(256, 4)
void fused_iter(int srcSel, int dstSel,
                const float* __restrict__ pred, const float* __restrict__ target) {
    __shared__ float xex[2][2][TYT][32];   // [parity][top/bot][ty][lane] x-plane y-exchange
    __shared__ float mex[2][2][TYT][32];   // same for M-plane

    const int lane = threadIdx.x;
    const int ty   = threadIdx.y;
    const int chunk = blockIdx.z % NCH;
    const int v     = blockIdx.z / NCH;
    const int zc    = chunk * CHZ;

    const int  gx      = blockIdx.x * OUT + lane - 2;
    const bool gx_in   = (unsigned)gx < (unsigned)DIM;
    const bool lane_out = (lane >= 2 && lane <= 29) && gx_in;

    int  gyv[YPT]; bool gy_in[YPT]; bool row_out[YPT]; int rowoff[YPT];
    #pragma unroll
    for (int j = 0; j < YPT; ++j) {
        int ly   = ty * YPT + j;
        gyv[j]   = blockIdx.y * OUT + ly - 2;
        gy_in[j] = (unsigned)gyv[j] < (unsigned)DIM;
        row_out[j] = (ly >= 2 && ly <= 29) && gy_in[j];
        rowoff[j]  = gyv[j] * DIM + gx;
    }

    const float* src;
    if (MODE == 0) src = (v < 2) ? target + (size_t)v * NVOX
                                 : pred + (size_t)(v - 2) * NVOX;
    else           src = g_buf[srcSel] + (size_t)v * NVOX;
    float* dst = g_buf[dstSel] + (size_t)v * NVOX;
    const float* other = nullptr;
    if (MODE == 2) other = (v < 2) ? pred + (size_t)v * NVOX
                                   : target + (size_t)(v - 2) * NVOX;

    const float PINF = __int_as_float(0x7f800000);
    const float NINF = -PINF;

    auto loadPlane = [&](int z, float xv[YPT]) {
        bool zin = (unsigned)z < (unsigned)DIM;
        #pragma unroll
        for (int j = 0; j < YPT; ++j)
            xv[j] = (zin && gx_in && gy_in[j])
                        ? __ldg(src + (size_t)z * SLICE + rowoff[j]) : PINF;
    };

    // rolling register planes
    float x_a[YPT], x_b[YPT], xnew[YPT];     // x(p-1), x(p), x(p+1)
    float m_prev[YPT];                        // M(p-1)
    float c_a[YPT], c_b[YPT];                 // C2(p-2), C2(p-1)

    loadPlane(zc - 2, x_a);
    loadPlane(zc - 1, x_b);
    xex[(zc - 1) & 1][0][ty][lane] = x_b[0];
    xex[(zc - 1) & 1][1][ty][lane] = x_b[3];
    #pragma unroll
    for (int j = 0; j < YPT; ++j) { m_prev[j] = NINF; c_a[j] = NINF; c_b[j] = NINF; }
    __syncthreads();

    double accS = 0.0, accP = 0.0;

    for (int p = zc - 1; p <= zc + CHZ; ++p) {
        // (a) load next x plane, (b) publish its y-boundary rows
        loadPlane(p + 1, xnew);
        xex[(p + 1) & 1][0][ty][lane] = xnew[0];
        xex[(p + 1) & 1][1][ty][lane] = xnew[3];

        // (c) 7-point min -> M(p), all in registers/shuffles (+2 boundary LDS)
        float mcur[YPT];
        {
            bool pin = (unsigned)p < (unsigned)DIM;
            float yup0 = (ty > 0)       ? xex[p & 1][1][ty - 1][lane] : PINF;
            float ydn3 = (ty < TYT - 1) ? xex[p & 1][0][ty + 1][lane] : PINF;
            #pragma unroll
            for (int j = 0; j < YPT; ++j) {
                float c  = x_b[j];
                float xl = __shfl_up_sync(FULL, c, 1);
                float xr = __shfl_down_sync(FULL, c, 1);
                float up = (j == 0)       ? yup0 : x_b[j - 1];
                float dn = (j == YPT - 1) ? ydn3 : x_b[j + 1];
                float m  = fminf(fminf(c, x_a[j]),
                                 fminf(xnew[j], fminf(xl, xr)));
                m = fminf(m, fminf(up, dn));
                mcur[j] = (pin && gx_in && gy_in[j]) ? m : NINF;
            }
        }
        // (d) publish M boundary rows
        mex[p & 1][0][ty][lane] = mcur[0];
        mex[p & 1][1][ty][lane] = mcur[3];
        __syncthreads();   // (e) the ONLY barrier per plane

        // (f) V = 3-y-max (registers), C2 = 3-x-max of V (shuffles)
        float mup = (ty > 0)       ? mex[p & 1][1][ty - 1][lane] : NINF;
        float mdn = (ty < TYT - 1) ? mex[p & 1][0][ty + 1][lane] : NINF;
        float cc[YPT];
        #pragma unroll
        for (int j = 0; j < YPT; ++j) {
            float up = (j == 0)       ? mup : mcur[j - 1];
            float dn = (j == YPT - 1) ? mdn : mcur[j + 1];
            float Vj = fmaxf(fmaxf(up, dn), mcur[j]);
            float vl = __shfl_up_sync(FULL, Vj, 1);
            float vr = __shfl_down_sync(FULL, Vj, 1);
            cc[j] = fmaxf(Vj, fmaxf(vl, vr));
        }

        // (g) emit plane q = p-1: A = z-max of C2, update, write/accumulate
        int q = p - 1;
        if (q >= zc && q < zc + CHZ) {
            #pragma unroll
            for (int j = 0; j < YPT; ++j) {
                if (row_out[j] && lane_out) {
                    float A       = fmaxf(fmaxf(c_a[j], c_b[j]), cc[j]);
                    float contour = fmaxf(A - m_prev[j], 0.0f);
                    float o       = fmaxf(x_a[j] - contour, 0.0f);
                    int gidx = q * SLICE + rowoff[j];
                    if (MODE < 2) {
                        dst[gidx] = o;
                    } else {
                        accS += (double)o;
                        accP += (double)(o * __ldg(other + gidx));
                    }
                }
            }
        }

        // (h) rotate register planes
        #pragma unroll
        for (int j = 0; j < YPT; ++j) {
            x_a[j] = x_b[j];  x_b[j] = xnew[j];
            c_a[j] = c_b[j];  c_b[j] = cc[j];
            m_prev[j] = mcur[j];
        }
    }

    if (MODE == 2) {
        #pragma unroll
        for (int off = 16; off > 0; off >>= 1) {
            accS += __shfl_down_sync(FULL, accS, off);
            accP += __shfl_down_sync(FULL, accP, off);
        }
        if (lane == 0) {
            if (v < 2) { atomicAdd(&g_acc[0], accP); atomicAdd(&g_acc[1], accS); }
            else       { atomicAdd(&g_acc[2], accP); atomicAdd(&g_acc[3], accS); }
        }
    }
}

__global__ void zero_acc_kernel() {
    if (threadIdx.x < 4) g_acc[threadIdx.x] = 0.0;
}

__global__ void final_kernel(float* __restrict__ out) {
    double clrecall = (g_acc[0] + 1e-12) / (g_acc[1] + 1e-12);
    double clacc    = (g_acc[2] + 1e-12) / (g_acc[3] + 1e-12);
    double cldice   = 2.0 * clrecall * clacc / (clrecall + clacc);
    out[0] = (float)(1.0 - cldice);
}

extern "C" void kernel_launch(void* const* d_in, const int* in_sizes, int n_in,
                              void* d_out, int out_size) {
    const float* pred   = (const float*)d_in[0];
    const float* target = (const float*)d_in[1];
    float* out = (float*)d_out;

    dim3 blk(32, TYT, 1);
    dim3 grd(NB, NB, 4 * NCH);

    zero_acc_kernel<<<1, 32>>>();
    fused_iter<0><<<grd, blk>>>(0, 0, pred, target);   // inputs -> buf0
    fused_iter<1><<<grd, blk>>>(0, 1, pred, target);   // buf0 -> buf1
    fused_iter<1><<<grd, blk>>>(1, 0, pred, target);   // buf1 -> buf0
    fused_iter<1><<<grd, blk>>>(0, 1, pred, target);   // buf0 -> buf1
    fused_iter<2><<<grd, blk>>>(1, 0, pred, target);   // buf1 -> sums
    final_kernel<<<1, 1>>>(out);
}

// round 5
// speedup vs baseline: 4.3934x; 1.0843x over previous
#include <cuda_runtime.h>
#include <math.h>

constexpr int DIM   = 192;
constexpr int SLICE = DIM * DIM;
constexpr int NVOX  = DIM * SLICE;

constexpr int TYT = 16;              // threads in y
constexpr int YPT = 2;               // rows per thread (tile height 32)
constexpr int OUT = 28;              // output span (32 - 2*2 halo)
constexpr int NB  = (DIM + OUT - 1) / OUT;   // 7
constexpr int CHZ = 16, NCH = DIM / CHZ;     // 12 z-chunks
constexpr unsigned FULL = 0xffffffffu;

__device__ float  g_buf[2][4 * NVOX];
__device__ double g_acc[4];  // {sum(skelT*pred), sum(skelT), sum(skelP*target), sum(skelP)}

__device__ __forceinline__ int slot3(int z) { return (z + 3) % 3; }  // valid z >= -3

// MODE 0: raw inputs -> dst ; MODE 1: buf -> buf ; MODE 2: buf -> sums
template <int MODE>
__global__ __launch_bounds__(512)
void fused_iter(int srcSel, int dstSel,
                const float* __restrict__ pred, const float* __restrict__ target) {
    __shared__ float xex[3][2][TYT][32];   // [slot][top/bot][ty][lane] x y-boundary rows
    __shared__ float mex[2][2][TYT][32];   // [parity][top/bot][ty][lane] M y-boundary rows

    const int lane = threadIdx.x;
    const int ty   = threadIdx.y;
    const int chunk = blockIdx.z % NCH;
    const int v     = blockIdx.z / NCH;
    const int zc    = chunk * CHZ;

    const int  gx       = blockIdx.x * OUT + lane - 2;
    const bool gx_in    = (unsigned)gx < (unsigned)DIM;
    const bool lane_out = (lane >= 2 && lane <= 29) && gx_in;

    int rowoff[YPT]; bool gy_in[YPT], row_out[YPT];
    #pragma unroll
    for (int j = 0; j < YPT; ++j) {
        int ly = ty * YPT + j;
        int gy = blockIdx.y * OUT + ly - 2;
        gy_in[j]   = (unsigned)gy < (unsigned)DIM;
        row_out[j] = (ly >= 2 && ly <= 29) && gy_in[j];
        rowoff[j]  = gy * DIM + gx;
    }

    const float* src;
    if (MODE == 0) src = (v < 2) ? target + (size_t)v * NVOX
                                 : pred + (size_t)(v - 2) * NVOX;
    else           src = g_buf[srcSel] + (size_t)v * NVOX;
    float* dst = g_buf[dstSel] + (size_t)v * NVOX;
    const float* other = nullptr;
    if (MODE == 2) other = (v < 2) ? pred + (size_t)v * NVOX
                                   : target + (size_t)(v - 2) * NVOX;

    const float PINF = __int_as_float(0x7f800000);
    const float NINF = -PINF;

    auto loadPlane = [&](int z, float xv[YPT]) {
        bool zin = (unsigned)z < (unsigned)DIM;
        #pragma unroll
        for (int j = 0; j < YPT; ++j)
            xv[j] = (zin && gx_in && gy_in[j])
                        ? __ldg(src + (size_t)z * SLICE + rowoff[j]) : PINF;
    };

    // rolling register planes: x(p-1), x(p), x(p+1), x(p+2)-incoming
    float x_a[YPT], x_b[YPT], x_c[YPT], x_d[YPT];
    float m_prev[YPT];         // M(p-1)
    float c_a[YPT], c_b[YPT];  // C2(p-2), C2(p-1)

    loadPlane(zc - 2, x_a);
    loadPlane(zc - 1, x_b);
    loadPlane(zc,     x_c);
    {
        int s1 = slot3(zc - 1), s2 = slot3(zc);
        xex[s1][0][ty][lane] = x_b[0];
        xex[s1][1][ty][lane] = x_b[YPT - 1];
        xex[s2][0][ty][lane] = x_c[0];
        xex[s2][1][ty][lane] = x_c[YPT - 1];
    }
    #pragma unroll
    for (int j = 0; j < YPT; ++j) { m_prev[j] = NINF; c_a[j] = NINF; c_b[j] = NINF; }
    __syncthreads();

    double accS = 0.0, accP = 0.0;

    for (int p = zc - 1; p <= zc + CHZ; ++p) {
        // (a) prefetch plane p+2 (consumed one plane-step later) + publish its rows
        loadPlane(p + 2, x_d);
        int sw = slot3(p + 2);
        xex[sw][0][ty][lane] = x_d[0];
        xex[sw][1][ty][lane] = x_d[YPT - 1];

        // (b) 7-pt min -> M(p) from resident x_a/x_b/x_c
        float mcur[YPT];
        {
            bool pin = (unsigned)p < (unsigned)DIM;
            int  sr  = slot3(p);
            float yup = (ty > 0)       ? xex[sr][1][ty - 1][lane] : PINF;
            float ydn = (ty < TYT - 1) ? xex[sr][0][ty + 1][lane] : PINF;
            #pragma unroll
            for (int j = 0; j < YPT; ++j) {
                float c  = x_b[j];
                float xl = __shfl_up_sync(FULL, c, 1);
                float xr = __shfl_down_sync(FULL, c, 1);
                float up = (j == 0)       ? yup : x_b[j - 1];
                float dn = (j == YPT - 1) ? ydn : x_b[j + 1];
                float m  = fminf(fminf(c, x_a[j]),
                                 fminf(x_c[j], fminf(xl, xr)));
                m = fminf(m, fminf(up, dn));
                mcur[j] = (pin && gx_in && gy_in[j]) ? m : NINF;
            }
        }
        int mp = p & 1;
        mex[mp][0][ty][lane] = mcur[0];
        mex[mp][1][ty][lane] = mcur[YPT - 1];
        __syncthreads();   // single barrier per plane

        // (c) V = 3-y-max, C2 = 3-x-max of V
        float mup = (ty > 0)       ? mex[mp][1][ty - 1][lane] : NINF;
        float mdn = (ty < TYT - 1) ? mex[mp][0][ty + 1][lane] : NINF;
        float cc[YPT];
        #pragma unroll
        for (int j = 0; j < YPT; ++j) {
            float up = (j == 0)       ? mup : mcur[j - 1];
            float dn = (j == YPT - 1) ? mdn : mcur[j + 1];
            float Vj = fmaxf(fmaxf(up, dn), mcur[j]);
            float vl = __shfl_up_sync(FULL, Vj, 1);
            float vr = __shfl_down_sync(FULL, Vj, 1);
            cc[j] = fmaxf(Vj, fmaxf(vl, vr));
        }

        // (d) emit plane q = p-1
        int q = p - 1;
        if (q >= zc && q < zc + CHZ) {
            #pragma unroll
            for (int j = 0; j < YPT; ++j) {
                if (row_out[j] && lane_out) {
                    float A       = fmaxf(fmaxf(c_a[j], c_b[j]), cc[j]);
                    float contour = fmaxf(A - m_prev[j], 0.0f);
                    float o       = fmaxf(x_a[j] - contour, 0.0f);
                    int gidx = q * SLICE + rowoff[j];
                    if (MODE < 2) {
                        dst[gidx] = o;
                    } else {
                        accS += (double)o;
                        accP += (double)(o * __ldg(other + gidx));
                    }
                }
            }
        }

        // (e) rotate
        #pragma unroll
        for (int j = 0; j < YPT; ++j) {
            x_a[j] = x_b[j]; x_b[j] = x_c[j]; x_c[j] = x_d[j];
            c_a[j] = c_b[j]; c_b[j] = cc[j];
            m_prev[j] = mcur[j];
        }
    }

    if (MODE == 2) {
        #pragma unroll
        for (int off = 16; off > 0; off >>= 1) {
            accS += __shfl_down_sync(FULL, accS, off);
            accP += __shfl_down_sync(FULL, accP, off);
        }
        if (lane == 0) {
            if (v < 2) { atomicAdd(&g_acc[0], accP); atomicAdd(&g_acc[1], accS); }
            else       { atomicAdd(&g_acc[2], accP); atomicAdd(&g_acc[3], accS); }
        }
    }
}

__global__ void zero_acc_kernel() {
    if (threadIdx.x < 4) g_acc[threadIdx.x] = 0.0;
}

__global__ void final_kernel(float* __restrict__ out) {
    double clrecall = (g_acc[0] + 1e-12) / (g_acc[1] + 1e-12);
    double clacc    = (g_acc[2] + 1e-12) / (g_acc[3] + 1e-12);
    double cldice   = 2.0 * clrecall * clacc / (clrecall + clacc);
    out[0] = (float)(1.0 - cldice);
}

extern "C" void kernel_launch(void* const* d_in, const int* in_sizes, int n_in,
                              void* d_out, int out_size) {
    const float* pred   = (const float*)d_in[0];
    const float* target = (const float*)d_in[1];
    float* out = (float*)d_out;

    dim3 blk(32, TYT, 1);
    dim3 grd(NB, NB, 4 * NCH);

    zero_acc_kernel<<<1, 32>>>();
    fused_iter<0><<<grd, blk>>>(0, 0, pred, target);   // inputs -> buf0
    fused_iter<1><<<grd, blk>>>(0, 1, pred, target);   // buf0 -> buf1
    fused_iter<1><<<grd, blk>>>(1, 0, pred, target);   // buf1 -> buf0
    fused_iter<1><<<grd, blk>>>(0, 1, pred, target);   // buf0 -> buf1
    fused_iter<2><<<grd, blk>>>(1, 0, pred, target);   // buf1 -> sums
    final_kernel<<<1, 1>>>(out);
}

// round 8
// speedup vs baseline: 5.5374x; 1.2604x over previous
#include <cuda_runtime.h>
#include <math.h>

constexpr int DIM   = 192;
constexpr int SLICE = DIM * DIM;
constexpr int NVOX  = DIM * SLICE;

constexpr int OUT = 28;                      // output span per tile (32 - 2*2 halo)
constexpr int NB  = (DIM + OUT - 1) / OUT;   // 7
constexpr int CHZ = 24, NCH = DIM / CHZ;     // 8 z-chunks
constexpr unsigned FULL = 0xffffffffu;

__device__ float  g_buf[2][4 * NVOX];
__device__ double g_acc[4];  // {sum(skelT*pred), sum(skelT), sum(skelP*target), sum(skelP)}

// MODE 0: raw inputs -> dst ; MODE 1: buf -> buf ; MODE 2: buf -> sums
template <int MODE>
__global__ __launch_bounds__(256)
void fused_iter(int srcSel, int dstSel,
                const float* __restrict__ pred, const float* __restrict__ target) {
    // y-boundary row exchange; float2 = the thread's two adjacent x columns
    __shared__ float2 xex[4][2][16][16];   // [slot][top/bot][ty][tx]
    __shared__ float2 mex[2][2][16][16];   // [parity][top/bot][ty][tx]

    const int tx = threadIdx.x;            // 0..15, owns x = 2tx, 2tx+1 (footprint 32)
    const int ty = threadIdx.y;            // 0..15, owns y = 2ty, 2ty+1 (footprint 32)
    const int chunk = blockIdx.z % NCH;
    const int v     = blockIdx.z / NCH;
    const int zc    = chunk * CHZ;

    const int gx0 = blockIdx.x * OUT + 2 * tx - 2;
    const int gy0 = blockIdx.y * OUT + 2 * ty - 2;
    bool gxin[2], gyin[2], colout[2], rowout[2];
    gxin[0] = (unsigned)gx0 < (unsigned)DIM;
    gxin[1] = (unsigned)(gx0 + 1) < (unsigned)DIM;
    gyin[0] = (unsigned)gy0 < (unsigned)DIM;
    gyin[1] = (unsigned)(gy0 + 1) < (unsigned)DIM;
    const int lx0 = 2 * tx, ly0 = 2 * ty;
    colout[0] = (lx0 >= 2 && lx0 <= 29) && gxin[0];
    colout[1] = (lx0 + 1 >= 2 && lx0 + 1 <= 29) && gxin[1];
    rowout[0] = (ly0 >= 2 && ly0 <= 29) && gyin[0];
    rowout[1] = (ly0 + 1 >= 2 && ly0 + 1 <= 29) && gyin[1];
    int off[2][2];
    off[0][0] = gy0 * DIM + gx0;  off[0][1] = off[0][0] + 1;
    off[1][0] = off[0][0] + DIM;  off[1][1] = off[1][0] + 1;

    const float* src;
    if (MODE == 0) src = (v < 2) ? target + (size_t)v * NVOX
                                 : pred + (size_t)(v - 2) * NVOX;
    else           src = g_buf[srcSel] + (size_t)v * NVOX;
    float* dst = g_buf[dstSel] + (size_t)v * NVOX;
    const float* other = nullptr;
    if (MODE == 2) other = (v < 2) ? pred + (size_t)v * NVOX
                                   : target + (size_t)(v - 2) * NVOX;

    const float PINF = __int_as_float(0x7f800000);
    const float NINF = -PINF;

    auto loadPlane = [&](int z, float xv[2][2]) {
        bool zin = (unsigned)z < (unsigned)DIM;
        const float* sp = src + (size_t)z * SLICE;
        #pragma unroll
        for (int j = 0; j < 2; ++j) {
            if (zin && gyin[j]) {
                if (gxin[0] && gxin[1]) {
                    float2 t = __ldg((const float2*)(sp + off[j][0]));
                    xv[j][0] = t.x; xv[j][1] = t.y;
                } else {
                    xv[j][0] = gxin[0] ? __ldg(sp + off[j][0]) : PINF;
                    xv[j][1] = gxin[1] ? __ldg(sp + off[j][1]) : PINF;
                }
            } else {
                xv[j][0] = PINF; xv[j][1] = PINF;
            }
        }
    };

    float xa[2][2], xb[2][2], xc[2][2], xd[2][2];
    float mp_[2][2], ca[2][2], cb[2][2];

    loadPlane(zc - 2, xa);
    loadPlane(zc - 1, xb);
    loadPlane(zc,     xc);
    {
        int s1 = (zc - 1 + 8) & 3, s2 = (zc + 8) & 3;
        xex[s1][0][ty][tx] = make_float2(xb[0][0], xb[0][1]);
        xex[s1][1][ty][tx] = make_float2(xb[1][0], xb[1][1]);
        xex[s2][0][ty][tx] = make_float2(xc[0][0], xc[0][1]);
        xex[s2][1][ty][tx] = make_float2(xc[1][0], xc[1][1]);
    }
    #pragma unroll
    for (int j = 0; j < 2; ++j)
        #pragma unroll
        for (int k = 0; k < 2; ++k) { mp_[j][k] = NINF; ca[j][k] = NINF; cb[j][k] = NINF; }
    __syncthreads();

    float accS = 0.0f, accP = 0.0f;

    #pragma unroll 2
    for (int p = zc - 1; p <= zc + CHZ; ++p) {
        // (a) prefetch plane p+2 (consumed one plane-step later) + publish rows
        loadPlane(p + 2, xd);
        int sw = (p + 2 + 8) & 3;
        xex[sw][0][ty][tx] = make_float2(xd[0][0], xd[0][1]);
        xex[sw][1][ty][tx] = make_float2(xd[1][0], xd[1][1]);

        // (b) 7-pt min -> M(p) from resident xa/xb/xc
        float m[2][2];
        {
            int sp_ = (p + 8) & 3;
            float2 yup = (ty > 0)  ? xex[sp_][1][ty - 1][tx] : make_float2(PINF, PINF);
            float2 ydn = (ty < 15) ? xex[sp_][0][ty + 1][tx] : make_float2(PINF, PINF);
            bool pin = (unsigned)p < (unsigned)DIM;
            #pragma unroll
            for (int j = 0; j < 2; ++j) {
                float vL = __shfl_up_sync(FULL, xb[j][1], 1, 16);
                if (tx == 0)  vL = PINF;
                float vR = __shfl_down_sync(FULL, xb[j][0], 1, 16);
                if (tx == 15) vR = PINF;
                float up0 = (j == 0) ? yup.x : xb[0][0];
                float up1 = (j == 0) ? yup.y : xb[0][1];
                float dn0 = (j == 1) ? ydn.x : xb[1][0];
                float dn1 = (j == 1) ? ydn.y : xb[1][1];
                float t  = fminf(xb[j][0], xb[j][1]);
                float m0 = fminf(fminf(t, vL), fminf(xa[j][0], xc[j][0]));
                m0 = fminf(m0, fminf(up0, dn0));
                float m1 = fminf(fminf(t, vR), fminf(xa[j][1], xc[j][1]));
                m1 = fminf(m1, fminf(up1, dn1));
                m[j][0] = (pin && gyin[j] && gxin[0]) ? m0 : NINF;
                m[j][1] = (pin && gyin[j] && gxin[1]) ? m1 : NINF;
            }
        }
        int par = p & 1;
        mex[par][0][ty][tx] = make_float2(m[0][0], m[0][1]);
        mex[par][1][ty][tx] = make_float2(m[1][0], m[1][1]);
        __syncthreads();   // single barrier per plane

        // (c) V = 3-y-max, C2 = 3-x-max of V
        float cc[2][2];
        {
            float2 mup = (ty > 0)  ? mex[par][1][ty - 1][tx] : make_float2(NINF, NINF);
            float2 mdn = (ty < 15) ? mex[par][0][ty + 1][tx] : make_float2(NINF, NINF);
            float s0 = fmaxf(m[0][0], m[1][0]);
            float s1 = fmaxf(m[0][1], m[1][1]);
            float Vr[2][2];
            Vr[0][0] = fmaxf(mup.x, s0); Vr[0][1] = fmaxf(mup.y, s1);
            Vr[1][0] = fmaxf(s0, mdn.x); Vr[1][1] = fmaxf(s1, mdn.y);
            #pragma unroll
            for (int j = 0; j < 2; ++j) {
                float VL = __shfl_up_sync(FULL, Vr[j][1], 1, 16);
                if (tx == 0)  VL = NINF;
                float VR = __shfl_down_sync(FULL, Vr[j][0], 1, 16);
                if (tx == 15) VR = NINF;
                float u = fmaxf(Vr[j][0], Vr[j][1]);
                cc[j][0] = fmaxf(VL, u);
                cc[j][1] = fmaxf(u, VR);
            }
        }

        // (d) emit plane q = p-1
        int q = p - 1;
        if (q >= zc) {
            float o[2][2];
            #pragma unroll
            for (int j = 0; j < 2; ++j)
                #pragma unroll
                for (int k = 0; k < 2; ++k) {
                    float A   = fmaxf(fmaxf(ca[j][k], cb[j][k]), cc[j][k]);
                    float ctr = fmaxf(A - mp_[j][k], 0.0f);
                    o[j][k]   = fmaxf(xa[j][k] - ctr, 0.0f);
                }
            size_t base = (size_t)q * SLICE;
            if (MODE < 2) {
                #pragma unroll
                for (int j = 0; j < 2; ++j) {
                    if (rowout[j]) {
                        if (colout[0] && colout[1]) {
                            *(float2*)(dst + base + off[j][0]) = make_float2(o[j][0], o[j][1]);
                        } else {
                            if (colout[0]) dst[base + off[j][0]] = o[j][0];
                            if (colout[1]) dst[base + off[j][1]] = o[j][1];
                        }
                    }
                }
            } else {
                #pragma unroll
                for (int j = 0; j < 2; ++j)
                    #pragma unroll
                    for (int k = 0; k < 2; ++k)
                        if (rowout[j] && colout[k]) {
                            float f = o[j][k];
                            accS += f;
                            accP += f * __ldg(other + base + off[j][k]);
                        }
            }
        }

        // (e) rotate register planes
        #pragma unroll
        for (int j = 0; j < 2; ++j)
            #pragma unroll
            for (int k = 0; k < 2; ++k) {
                xa[j][k] = xb[j][k]; xb[j][k] = xc[j][k]; xc[j][k] = xd[j][k];
                ca[j][k] = cb[j][k]; cb[j][k] = cc[j][k];
                mp_[j][k] = m[j][k];
            }
    }

    if (MODE == 2) {
        #pragma unroll
        for (int offm = 16; offm > 0; offm >>= 1) {
            accS += __shfl_down_sync(FULL, accS, offm);
            accP += __shfl_down_sync(FULL, accP, offm);
        }
        int lane = (tx + ty * 16) & 31;
        if (lane == 0) {
            if (v < 2) { atomicAdd(&g_acc[0], (double)accP); atomicAdd(&g_acc[1], (double)accS); }
            else       { atomicAdd(&g_acc[2], (double)accP); atomicAdd(&g_acc[3], (double)accS); }
        }
    }
}

__global__ void zero_acc_kernel() {
    if (threadIdx.x < 4) g_acc[threadIdx.x] = 0.0;
}

__global__ void final_kernel(float* __restrict__ out) {
    double clrecall = (g_acc[0] + 1e-12) / (g_acc[1] + 1e-12);
    double clacc    = (g_acc[2] + 1e-12) / (g_acc[3] + 1e-12);
    double cldice   = 2.0 * clrecall * clacc / (clrecall + clacc);
    out[0] = (float)(1.0 - cldice);
}

extern "C" void kernel_launch(void* const* d_in, const int* in_sizes, int n_in,
                              void* d_out, int out_size) {
    const float* pred   = (const float*)d_in[0];
    const float* target = (const float*)d_in[1];
    float* out = (float*)d_out;

    dim3 blk(16, 16, 1);
    dim3 grd(NB, NB, 4 * NCH);

    zero_acc_kernel<<<1, 32>>>();
    fused_iter<0><<<grd, blk>>>(0, 0, pred, target);   // inputs -> buf0
    fused_iter<1><<<grd, blk>>>(0, 1, pred, target);   // buf0 -> buf1
    fused_iter<1><<<grd, blk>>>(1, 0, pred, target);   // buf1 -> buf0
    fused_iter<1><<<grd, blk>>>(0, 1, pred, target);   // buf0 -> buf1
    fused_iter<2><<<grd, blk>>>(1, 0, pred, target);   // buf1 -> sums
    final_kernel<<<1, 1>>>(out);
}